// round 14
// baseline (speedup 1.0000x reference)
#include <cuda_runtime.h>
#include <cuda_fp16.h>
#include <mma.h>
#include <cstdint>
#include <cstdlib>

using namespace nvcuda;

#define NN 50000
#define NE 800000
#define LN_EPS 1e-5f

// Only tiny globals: ~200KB. All large scratch lives inside d_out, row-locally.
__device__ float g_dinv[NN];
__device__ int   g_is64;

__attribute__((constructor)) static void set_eager_loading() {
    setenv("CUDA_MODULE_LOADING", "EAGER", 1);
}

// d_out row layout (per node, 1024 bytes = 256 floats = 512 halves):
//   L1a: t fp16 accum @ half[0,128)               (init_from_x + scat_x16)
//   L1b: gemm_l1: z=t@W1 (frags only) -> h fp16 @ half[256,512) + s_init @ half[0,256)
//   L2a: s fp16 accum @ half[0,256)               (scat_h16)
//   L2b: gemm_l2: u=LN(s@W2+b2)+pb (smem only) -> out = relu(u + x@projW) fp32 full row

// 128-bit fire-and-forget reduction (scatters are atomic-ISSUE-bound).
__device__ __forceinline__ void red_add_v4_f16x2(void* p, uint32_t a, uint32_t b,
                                                 uint32_t c, uint32_t d) {
    asm volatile("red.global.add.noftz.v4.f16x2 [%0], {%1, %2, %3, %4};"
                 :: "l"(p), "r"(a), "r"(b), "r"(c), "r"(d) : "memory");
}

// ---------------- edge dtype detect ----------------
__global__ void detect_kernel(const void* ei) {
    const long long* p = (const long long*)ei;
    int ok = 1;
    for (int i = 0; i < 64; i++) {
        long long v = p[i];
        if (v < 0 || v >= NN) { ok = 0; break; }
    }
    g_is64 = ok;
}

__device__ __forceinline__ int edge_at(const void* p, size_t idx, int is64) {
    if (is64) return (int)((const long long*)p)[idx];
    return ((const int*)p)[idx];
}

// ---------------- degree / dinv ----------------
__global__ void deg_init_kernel() {
    int i = blockIdx.x * blockDim.x + threadIdx.x;
    if (i < NN) g_dinv[i] = 1.0f;   // self-loop
}
__global__ void deg_count_kernel(const void* __restrict__ ei, int ne) {
    int e = blockIdx.x * blockDim.x + threadIdx.x;
    if (e < ne) atomicAdd(&g_dinv[edge_at(ei, (size_t)ne + e, g_is64)], 1.0f);
}
__global__ void deg_fin_kernel() {
    int i = blockIdx.x * blockDim.x + threadIdx.x;
    if (i < NN) g_dinv[i] = rsqrtf(g_dinv[i]);
}

// ---------------- L1 init: t = x * dinv^2 as fp16 @ half[0,128) ----------------
__global__ void init_from_x(const float* __restrict__ x, float* __restrict__ out) {
    int i = blockIdx.x * blockDim.x + threadIdx.x;
    if (i >= NN * 32) return;
    int n = i >> 5, c4 = i & 31;
    float d = g_dinv[n]; float w = d * d;
    float4 v = ((const float4*)x)[(size_t)n * 32 + c4];
    __half2* hp = (__half2*)((__half*)out + (size_t)n * 512 + c4 * 4);
    hp[0] = __floats2half2_rn(v.x * w, v.y * w);
    hp[1] = __floats2half2_rn(v.z * w, v.w * w);
}

// ---------------- L1 scatter: fp16 red, 2 edges/warp (16 lanes x 8 halves) --------
__global__ __launch_bounds__(256) void scat_x16(const void* __restrict__ ei,
                                                const float* __restrict__ x,
                                                float* __restrict__ out, int ne) {
    int gwarp = (blockIdx.x * blockDim.x + threadIdx.x) >> 5;
    int lane  = threadIdx.x & 31;
    int sub   = lane >> 4;
    int slane = lane & 15;
    int e = gwarp * 2 + sub;
    if (e >= ne) return;
    int is64 = g_is64;
    int r = edge_at(ei, e, is64);
    int c = edge_at(ei, (size_t)ne + e, is64);
    float w = g_dinv[r] * g_dinv[c];
    const float4* xp = (const float4*)(x + (size_t)r * 128) + slane * 2;
    float4 v0 = xp[0], v1 = xp[1];
    __half2 o0 = __floats2half2_rn(v0.x * w, v0.y * w);
    __half2 o1 = __floats2half2_rn(v0.z * w, v0.w * w);
    __half2 o2 = __floats2half2_rn(v1.x * w, v1.y * w);
    __half2 o3 = __floats2half2_rn(v1.z * w, v1.w * w);
    __half* d = (__half*)out + (size_t)c * 512 + slane * 8;
    red_add_v4_f16x2(d, *(uint32_t*)&o0, *(uint32_t*)&o1,
                        *(uint32_t*)&o2, *(uint32_t*)&o3);
}

// ---------------- L2 scatter: fp16 red (32 lanes x 8 halves, 256 ch/warp) ---------
__global__ __launch_bounds__(256) void scat_h16(const void* __restrict__ ei,
                                                float* __restrict__ out, int ne) {
    int warp = (blockIdx.x * blockDim.x + threadIdx.x) >> 5;
    int lane = threadIdx.x & 31;
    if (warp >= ne) return;
    int is64 = g_is64;
    int r = edge_at(ei, warp, is64);
    int c = edge_at(ei, (size_t)ne + warp, is64);
    float w = g_dinv[r] * g_dinv[c];
    const uint4* hp = (const uint4*)((const __half*)out + (size_t)r * 512 + 256) + lane;
    uint4 raw = *hp;
    __half2 h0 = *(__half2*)&raw.x, h1 = *(__half2*)&raw.y;
    __half2 h2 = *(__half2*)&raw.z, h3 = *(__half2*)&raw.w;
    float2 f0 = __half22float2(h0), f1 = __half22float2(h1);
    float2 f2 = __half22float2(h2), f3 = __half22float2(h3);
    __half2 o0 = __floats2half2_rn(f0.x * w, f0.y * w);
    __half2 o1 = __floats2half2_rn(f1.x * w, f1.y * w);
    __half2 o2 = __floats2half2_rn(f2.x * w, f2.y * w);
    __half2 o3 = __floats2half2_rn(f3.x * w, f3.y * w);
    __half* d = (__half*)out + (size_t)c * 512 + lane * 8;
    red_add_v4_f16x2(d, *(uint32_t*)&o0, *(uint32_t*)&o1,
                        *(uint32_t*)&o2, *(uint32_t*)&o3);
}

// ======== fused L1: z = t@W1 (frags) -> h = relu(LN(z+b1)) fp16 + s_init ========
// BM=32, BN=256, BK=16; 8 warps (2m x 4n), 1x4 frags each; z stays on-chip.
__global__ __launch_bounds__(256) void gemm_l1(
    float* __restrict__ out, const float* __restrict__ B,
    const float* __restrict__ bias, const float* __restrict__ gamma,
    const float* __restrict__ beta, int M)
{
    __shared__ alignas(16) __half As[32][24];
    __shared__ alignas(16) __half Bs[16][272];
    __shared__ alignas(16) float  Cs[32][256];
    int tid = threadIdx.x;
    int row0 = blockIdx.x * 32;
    int wid = tid >> 5;
    int lane = tid & 31;
    int warp_m = wid >> 2, warp_n = wid & 3;
    const __half* hA = (const __half*)out;

    wmma::fragment<wmma::accumulator, 16, 16, 16, float> cfrag[4];
    #pragma unroll
    for (int j = 0; j < 4; j++) wmma::fill_fragment(cfrag[j], 0.0f);

    for (int kt = 0; kt < 128; kt += 16) {
        if (tid < 128) {
            int r = tid >> 2, c = (tid & 3) * 4;
            int gr = row0 + r;
            __half2 p0, p1;
            if (gr < M) {
                uint2 raw = *(const uint2*)(hA + (size_t)gr * 512 + kt + c);
                p0 = *(__half2*)&raw.x; p1 = *(__half2*)&raw.y;
            } else { p0 = __floats2half2_rn(0.f, 0.f); p1 = p0; }
            *(__half2*)&As[r][c] = p0;
            *(__half2*)&As[r][c + 2] = p1;
        }
        #pragma unroll
        for (int i = tid; i < 512; i += 256) {
            int r = i >> 5, c = (i & 31) * 8;
            float4 v0 = *(const float4*)&B[(size_t)(kt + r) * 256 + c];
            float4 v1 = *(const float4*)&B[(size_t)(kt + r) * 256 + c + 4];
            *(__half2*)&Bs[r][c]     = __floats2half2_rn(v0.x, v0.y);
            *(__half2*)&Bs[r][c + 2] = __floats2half2_rn(v0.z, v0.w);
            *(__half2*)&Bs[r][c + 4] = __floats2half2_rn(v1.x, v1.y);
            *(__half2*)&Bs[r][c + 6] = __floats2half2_rn(v1.z, v1.w);
        }
        __syncthreads();
        wmma::fragment<wmma::matrix_a, 16, 16, 16, __half, wmma::row_major> afrag;
        wmma::fragment<wmma::matrix_b, 16, 16, 16, __half, wmma::row_major> bfrag;
        wmma::load_matrix_sync(afrag, &As[warp_m * 16][0], 24);
        #pragma unroll
        for (int j = 0; j < 4; j++) {
            wmma::load_matrix_sync(bfrag, &Bs[0][warp_n * 64 + j * 16], 272);
            wmma::mma_sync(cfrag[j], afrag, bfrag, cfrag[j]);
        }
        __syncthreads();
    }

    // frags -> smem
    #pragma unroll
    for (int j = 0; j < 4; j++)
        wmma::store_matrix_sync(&Cs[warp_m * 16][warp_n * 64 + j * 16],
                                cfrag[j], 256, wmma::mem_row_major);
    __syncthreads();

    // LN: each warp handles 4 rows
    #pragma unroll
    for (int i = 0; i < 4; i++) {
        int lr = wid * 4 + i;
        int gr = row0 + lr;
        if (gr >= M) break;
        float dv = g_dinv[gr];
        float w2 = dv * dv;
        float v[8];
        #pragma unroll
        for (int k = 0; k < 2; k++) {
            int f4 = lane + k * 32;
            float4 t = ((const float4*)&Cs[lr][0])[f4];
            float4 bb = ((const float4*)bias)[f4];
            v[k*4+0] = t.x + bb.x; v[k*4+1] = t.y + bb.y;
            v[k*4+2] = t.z + bb.z; v[k*4+3] = t.w + bb.w;
        }
        float s = 0.f, s2 = 0.f;
        #pragma unroll
        for (int k = 0; k < 8; k++) { s += v[k]; s2 += v[k] * v[k]; }
        #pragma unroll
        for (int o = 16; o > 0; o >>= 1) {
            s  += __shfl_xor_sync(0xFFFFFFFF, s,  o);
            s2 += __shfl_xor_sync(0xFFFFFFFF, s2, o);
        }
        float mean = s * (1.0f / 256.0f);
        float var  = s2 * (1.0f / 256.0f) - mean * mean;
        float rs   = rsqrtf(var + LN_EPS);
        #pragma unroll
        for (int k = 0; k < 2; k++) {
            int f4 = lane + k * 32;
            float4 gm = ((const float4*)gamma)[f4];
            float4 bt = ((const float4*)beta)[f4];
            float o0 = fmaxf((v[k*4+0]-mean)*rs*gm.x + bt.x, 0.f);
            float o1 = fmaxf((v[k*4+1]-mean)*rs*gm.y + bt.y, 0.f);
            float o2 = fmaxf((v[k*4+2]-mean)*rs*gm.z + bt.z, 0.f);
            float o3 = fmaxf((v[k*4+3]-mean)*rs*gm.w + bt.w, 0.f);
            __half2* hp = (__half2*)((__half*)out + (size_t)gr * 512 + 256 + f4 * 4);
            hp[0] = __floats2half2_rn(o0, o1);
            hp[1] = __floats2half2_rn(o2, o3);
            __half2* sp = (__half2*)((__half*)out + (size_t)gr * 512 + f4 * 4);
            sp[0] = __floats2half2_rn(o0 * w2, o1 * w2);
            sp[1] = __floats2half2_rn(o2 * w2, o3 * w2);
        }
    }
}

// ==== fused L2+proj: u = LN(s@W2 + b2)+pb (smem) ; out = relu(u + x@projW) ====
__global__ __launch_bounds__(256) void gemm_l2(
    float* __restrict__ out, const float* __restrict__ W2,
    const float* __restrict__ b2, const float* __restrict__ gamma,
    const float* __restrict__ beta, const float* __restrict__ pb,
    const float* __restrict__ x, const float* __restrict__ projW, int M)
{
    __shared__ alignas(16) __half As[32][24];
    __shared__ alignas(16) __half Bs[16][272];
    __shared__ alignas(16) float  Cs[32][256];
    int tid = threadIdx.x;
    int row0 = blockIdx.x * 32;
    int wid = tid >> 5;
    int lane = tid & 31;
    int warp_m = wid >> 2, warp_n = wid & 3;
    const __half* hA = (const __half*)out;

    wmma::fragment<wmma::accumulator, 16, 16, 16, float> cfrag[4];
    #pragma unroll
    for (int j = 0; j < 4; j++) wmma::fill_fragment(cfrag[j], 0.0f);

    // ---- pass 1: s @ W2, K=256, A fp16 @ half[0,256) pitch 512 ----
    for (int kt = 0; kt < 256; kt += 16) {
        if (tid < 128) {
            int r = tid >> 2, c = (tid & 3) * 4;
            int gr = row0 + r;
            __half2 p0, p1;
            if (gr < M) {
                uint2 raw = *(const uint2*)(hA + (size_t)gr * 512 + kt + c);
                p0 = *(__half2*)&raw.x; p1 = *(__half2*)&raw.y;
            } else { p0 = __floats2half2_rn(0.f, 0.f); p1 = p0; }
            *(__half2*)&As[r][c] = p0;
            *(__half2*)&As[r][c + 2] = p1;
        }
        #pragma unroll
        for (int i = tid; i < 512; i += 256) {
            int r = i >> 5, c = (i & 31) * 8;
            float4 v0 = *(const float4*)&W2[(size_t)(kt + r) * 256 + c];
            float4 v1 = *(const float4*)&W2[(size_t)(kt + r) * 256 + c + 4];
            *(__half2*)&Bs[r][c]     = __floats2half2_rn(v0.x, v0.y);
            *(__half2*)&Bs[r][c + 2] = __floats2half2_rn(v0.z, v0.w);
            *(__half2*)&Bs[r][c + 4] = __floats2half2_rn(v1.x, v1.y);
            *(__half2*)&Bs[r][c + 6] = __floats2half2_rn(v1.z, v1.w);
        }
        __syncthreads();
        wmma::fragment<wmma::matrix_a, 16, 16, 16, __half, wmma::row_major> afrag;
        wmma::fragment<wmma::matrix_b, 16, 16, 16, __half, wmma::row_major> bfrag;
        wmma::load_matrix_sync(afrag, &As[warp_m * 16][0], 24);
        #pragma unroll
        for (int j = 0; j < 4; j++) {
            wmma::load_matrix_sync(bfrag, &Bs[0][warp_n * 64 + j * 16], 272);
            wmma::mma_sync(cfrag[j], afrag, bfrag, cfrag[j]);
        }
        __syncthreads();
    }

    // ---- interlude: LN in smem ----
    #pragma unroll
    for (int j = 0; j < 4; j++)
        wmma::store_matrix_sync(&Cs[warp_m * 16][warp_n * 64 + j * 16],
                                cfrag[j], 256, wmma::mem_row_major);
    __syncthreads();

    #pragma unroll
    for (int i = 0; i < 4; i++) {
        int lr = wid * 4 + i;
        int gr = row0 + lr;
        if (gr >= M) break;
        float v[8];
        #pragma unroll
        for (int k = 0; k < 2; k++) {
            int f4 = lane + k * 32;
            float4 t = ((const float4*)&Cs[lr][0])[f4];
            float4 bb = ((const float4*)b2)[f4];
            v[k*4+0] = t.x + bb.x; v[k*4+1] = t.y + bb.y;
            v[k*4+2] = t.z + bb.z; v[k*4+3] = t.w + bb.w;
        }
        float s = 0.f, s2 = 0.f;
        #pragma unroll
        for (int k = 0; k < 8; k++) { s += v[k]; s2 += v[k] * v[k]; }
        #pragma unroll
        for (int o = 16; o > 0; o >>= 1) {
            s  += __shfl_xor_sync(0xFFFFFFFF, s,  o);
            s2 += __shfl_xor_sync(0xFFFFFFFF, s2, o);
        }
        float mean = s * (1.0f / 256.0f);
        float var  = s2 * (1.0f / 256.0f) - mean * mean;
        float rs   = rsqrtf(var + LN_EPS);
        #pragma unroll
        for (int k = 0; k < 2; k++) {
            int f4 = lane + k * 32;
            float4 gm = ((const float4*)gamma)[f4];
            float4 bt = ((const float4*)beta)[f4];
            float4 pv = ((const float4*)pb)[f4];
            float4 o;
            o.x = (v[k*4+0]-mean)*rs*gm.x + bt.x + pv.x;
            o.y = (v[k*4+1]-mean)*rs*gm.y + bt.y + pv.y;
            o.z = (v[k*4+2]-mean)*rs*gm.z + bt.z + pv.z;
            o.w = (v[k*4+3]-mean)*rs*gm.w + bt.w + pv.w;
            ((float4*)&Cs[lr][0])[f4] = o;
        }
    }
    __syncthreads();

    // reload u as accumulator base
    #pragma unroll
    for (int j = 0; j < 4; j++)
        wmma::load_matrix_sync(cfrag[j], &Cs[warp_m * 16][warp_n * 64 + j * 16],
                               256, wmma::mem_row_major);
    __syncthreads();

    // ---- pass 2: += x @ projW, K=128, A fp32 pitch 128 ----
    for (int kt = 0; kt < 128; kt += 16) {
        if (tid < 128) {
            int r = tid >> 2, c = (tid & 3) * 4;
            int gr = row0 + r;
            __half2 p0, p1;
            if (gr < M) {
                float4 v = *(const float4*)(x + (size_t)gr * 128 + kt + c);
                p0 = __floats2half2_rn(v.x, v.y);
                p1 = __floats2half2_rn(v.z, v.w);
            } else { p0 = __floats2half2_rn(0.f, 0.f); p1 = p0; }
            *(__half2*)&As[r][c] = p0;
            *(__half2*)&As[r][c + 2] = p1;
        }
        #pragma unroll
        for (int i = tid; i < 512; i += 256) {
            int r = i >> 5, c = (i & 31) * 8;
            float4 v0 = *(const float4*)&projW[(size_t)(kt + r) * 256 + c];
            float4 v1 = *(const float4*)&projW[(size_t)(kt + r) * 256 + c + 4];
            *(__half2*)&Bs[r][c]     = __floats2half2_rn(v0.x, v0.y);
            *(__half2*)&Bs[r][c + 2] = __floats2half2_rn(v0.z, v0.w);
            *(__half2*)&Bs[r][c + 4] = __floats2half2_rn(v1.x, v1.y);
            *(__half2*)&Bs[r][c + 6] = __floats2half2_rn(v1.z, v1.w);
        }
        __syncthreads();
        wmma::fragment<wmma::matrix_a, 16, 16, 16, __half, wmma::row_major> afrag;
        wmma::fragment<wmma::matrix_b, 16, 16, 16, __half, wmma::row_major> bfrag;
        wmma::load_matrix_sync(afrag, &As[warp_m * 16][0], 24);
        #pragma unroll
        for (int j = 0; j < 4; j++) {
            wmma::load_matrix_sync(bfrag, &Bs[0][warp_n * 64 + j * 16], 272);
            wmma::mma_sync(cfrag[j], afrag, bfrag, cfrag[j]);
        }
        __syncthreads();
    }

    // relu + store
    int fr = row0 + warp_m * 16;
    if (fr + 16 <= M) {
        #pragma unroll
        for (int j = 0; j < 4; j++) {
            #pragma unroll
            for (int e = 0; e < cfrag[j].num_elements; e++)
                cfrag[j].x[e] = fmaxf(cfrag[j].x[e], 0.0f);
            wmma::store_matrix_sync(&out[(size_t)fr * 256 + warp_n * 64 + j * 16],
                                    cfrag[j], 256, wmma::mem_row_major);
        }
    }
}

// ---------------- prewarm (best effort; all errors swallowed) ----------------
namespace {
struct Prewarm {
    Prewarm() {
        float* s = nullptr;
        cudaGetSymbolAddress((void**)&s, g_dinv);
        if (!s) { cudaGetLastError(); return; }
        detect_kernel<<<1, 1>>>(s);
        deg_init_kernel<<<(NN + 255) / 256, 256>>>();
        deg_fin_kernel<<<(NN + 255) / 256, 256>>>();
        cudaDeviceSynchronize();
        cudaGetLastError();
    }
};
static Prewarm g_prewarm;
}

// ---------------- launch ----------------
extern "C" void kernel_launch(void* const* d_in, const int* in_sizes, int n_in,
                              void* d_out, int out_size)
{
    const float* x      = (const float*)d_in[0];
    const void*  ei     = d_in[1];
    const float* W1     = (const float*)d_in[2];
    const float* b1     = (const float*)d_in[3];
    const float* W2     = (const float*)d_in[4];
    const float* b2     = (const float*)d_in[5];
    const float* ln1_g  = (const float*)d_in[6];
    const float* ln1_b  = (const float*)d_in[7];
    const float* ln2_g  = (const float*)d_in[8];
    const float* ln2_b  = (const float*)d_in[9];
    const float* proj_W = (const float*)d_in[10];
    const float* proj_b = (const float*)d_in[11];
    float* out = (float*)d_out;

    int nb_n    = (NN + 255) / 256;
    int nb_el   = (NN * 32 + 255) / 256;
    int nb_sc   = (NE * 32 + 255) / 256;       // 1 edge/warp (L2)
    int nb_sc2  = (NE * 16 + 255) / 256;       // 2 edges/warp (L1)
    int nb_g    = (NN + 31) / 32;

    detect_kernel<<<1, 1>>>(ei);
    deg_init_kernel<<<nb_n, 256>>>();
    deg_count_kernel<<<(NE + 255) / 256, 256>>>(ei, NE);
    deg_fin_kernel<<<nb_n, 256>>>();

    // ---- layer 1: t = A_hat x (fp16 accum) ; fused z=t@W1 + LN -> h, s_init ----
    init_from_x<<<nb_el, 256>>>(x, out);
    scat_x16<<<nb_sc2, 256>>>(ei, x, out, NE);
    gemm_l1<<<nb_g, 256>>>(out, W1, b1, ln1_g, ln1_b, NN);

    // ---- layer 2: s = A_hat h (fp16 accum) ; fused u=LN(s@W2+b2)+pb, out=relu(u+x@pW) ----
    scat_h16<<<nb_sc, 256>>>(ei, out, NE);
    gemm_l2<<<nb_g, 256>>>(out, W2, b2, ln2_g, ln2_b, proj_b, x, proj_W, NN);
}

// round 15
// speedup vs baseline: 1.0309x; 1.0309x over previous
#include <cuda_runtime.h>
#include <cuda_fp16.h>
#include <mma.h>
#include <cstdint>
#include <cstdlib>

using namespace nvcuda;

#define NN 50000
#define NE 800000
#define LN_EPS 1e-5f

// Small globals (~3.6MB): CSR of the fixed graph + dinv. Large scratch stays in d_out.
__device__ float g_dinv[NN];
__device__ int   g_cnt[NN];          // counts, then fill-cursors
__device__ int   g_rowptr[NN + 1];
__device__ int   g_csr[NE];          // source node per edge, grouped by dest
__device__ int   g_is64;

__attribute__((constructor)) static void set_eager_loading() {
    setenv("CUDA_MODULE_LOADING", "EAGER", 1);
}

// d_out row layout (per node, 1024 bytes = 256 floats = 512 halves):
//   L1a: t fp16 @ half[0,128)                 (gather_x: fp32 accum in regs, fp16 store)
//   L1b: z fp32 @ float[0,256)                (gemm_wmma<0>, in place)
//   L1c: h fp16 @ half[256,512)               (ln_to_h)
//   L2a: s fp16 @ half[0,256)                 (gather_h: fp32 accum, fp16 store)
//   L2b: u fp32 @ float[0,256)                (gemm_wmma<1>, in place)
//   L2c: u = LN(u+b2) + proj_b                (ln_inplace)
//   fin: out = relu(u + x@projW)              (gemm_wmma<2>, C-accum + relu)

// ---------------- edge dtype detect ----------------
__global__ void detect_kernel(const void* ei) {
    const long long* p = (const long long*)ei;
    int ok = 1;
    for (int i = 0; i < 64; i++) {
        long long v = p[i];
        if (v < 0 || v >= NN) { ok = 0; break; }
    }
    g_is64 = ok;
}

__device__ __forceinline__ int edge_at(const void* p, size_t idx, int is64) {
    if (is64) return (int)((const long long*)p)[idx];
    return ((const int*)p)[idx];
}

// ---------------- CSR build ----------------
__global__ void zero_cnt_kernel() {
    int i = blockIdx.x * blockDim.x + threadIdx.x;
    if (i < NN) g_cnt[i] = 0;
}
__global__ void deg_count_kernel(const void* __restrict__ ei, int ne) {
    int e = blockIdx.x * blockDim.x + threadIdx.x;
    if (e < ne) atomicAdd(&g_cnt[edge_at(ei, (size_t)ne + e, g_is64)], 1);
}
// One-block scan: cnt -> rowptr (exclusive) + cursor (=rowptr) + dinv.
__global__ __launch_bounds__(1024) void scan_kernel() {
    __shared__ int ssum[1024];
    int t = threadIdx.x;
    const int CH = (NN + 1023) / 1024;   // 49
    int start = t * CH;
    int end = min(start + CH, NN);
    int local = 0;
    for (int i = start; i < end; i++) {
        int c = g_cnt[i];
        g_dinv[i] = rsqrtf((float)c + 1.0f);   // +1 self-loop
        local += c;
    }
    ssum[t] = local;
    __syncthreads();
    for (int off = 1; off < 1024; off <<= 1) {
        int v = (t >= off) ? ssum[t - off] : 0;
        __syncthreads();
        ssum[t] += v;
        __syncthreads();
    }
    int run = (t == 0) ? 0 : ssum[t - 1];
    for (int i = start; i < end; i++) {
        int c = g_cnt[i];
        g_rowptr[i] = run;
        g_cnt[i] = run;     // cursor for fill
        run += c;
    }
    if (t == 1023) g_rowptr[NN] = run;
}
__global__ void fill_kernel(const void* __restrict__ ei, int ne) {
    int e = blockIdx.x * blockDim.x + threadIdx.x;
    if (e >= ne) return;
    int is64 = g_is64;
    int r = edge_at(ei, e, is64);
    int c = edge_at(ei, (size_t)ne + e, is64);
    int pos = atomicAdd(&g_cnt[c], 1);
    g_csr[pos] = r;
}

// ---------------- L1 gather: t[n] = sum_{src->n} w*x[src] + dinv^2*x[n], fp16 out ---
// one warp per node; lane owns 4 channels (float4 of x).
__global__ __launch_bounds__(256) void gather_x(const float* __restrict__ x,
                                                float* __restrict__ out) {
    int n = (blockIdx.x * blockDim.x + threadIdx.x) >> 5;
    int lane = threadIdx.x & 31;
    if (n >= NN) return;
    float dn = g_dinv[n];
    int start = g_rowptr[n], end = g_rowptr[n + 1];
    float w0 = dn * dn;
    float4 vs = ((const float4*)x)[(size_t)n * 32 + lane];
    float a0 = vs.x * w0, a1 = vs.y * w0, a2 = vs.z * w0, a3 = vs.w * w0;
    for (int e0 = start; e0 < end; e0 += 32) {
        int nrem = min(32, end - e0);
        int src = 0; float dsrc = 0.f;
        if (lane < nrem) { src = g_csr[e0 + lane]; dsrc = g_dinv[src]; }
        for (int j = 0; j < nrem; j++) {
            int s = __shfl_sync(0xFFFFFFFF, src, j);
            float w = __shfl_sync(0xFFFFFFFF, dsrc, j) * dn;
            float4 v = ((const float4*)x)[(size_t)s * 32 + lane];
            a0 += v.x * w; a1 += v.y * w; a2 += v.z * w; a3 += v.w * w;
        }
    }
    __half2* hp = (__half2*)((__half*)out + (size_t)n * 512 + lane * 4);
    hp[0] = __floats2half2_rn(a0, a1);
    hp[1] = __floats2half2_rn(a2, a3);
}

// ---------------- L2 gather: s[n] = sum w*h[src] + dinv^2*h[n]; h fp16 @ [256,512) --
// one warp per node; lane owns 8 channels (uint4 of halves).
__global__ __launch_bounds__(256) void gather_h(float* __restrict__ out) {
    int n = (blockIdx.x * blockDim.x + threadIdx.x) >> 5;
    int lane = threadIdx.x & 31;
    if (n >= NN) return;
    float dn = g_dinv[n];
    int start = g_rowptr[n], end = g_rowptr[n + 1];
    float w0 = dn * dn;
    const __half* hbase = (const __half*)out;
    float acc[8];
    {
        uint4 raw = *((const uint4*)(hbase + (size_t)n * 512 + 256) + lane);
        float2 f0 = __half22float2(*(__half2*)&raw.x);
        float2 f1 = __half22float2(*(__half2*)&raw.y);
        float2 f2 = __half22float2(*(__half2*)&raw.z);
        float2 f3 = __half22float2(*(__half2*)&raw.w);
        acc[0] = f0.x * w0; acc[1] = f0.y * w0; acc[2] = f1.x * w0; acc[3] = f1.y * w0;
        acc[4] = f2.x * w0; acc[5] = f2.y * w0; acc[6] = f3.x * w0; acc[7] = f3.y * w0;
    }
    for (int e0 = start; e0 < end; e0 += 32) {
        int nrem = min(32, end - e0);
        int src = 0; float dsrc = 0.f;
        if (lane < nrem) { src = g_csr[e0 + lane]; dsrc = g_dinv[src]; }
        for (int j = 0; j < nrem; j++) {
            int s = __shfl_sync(0xFFFFFFFF, src, j);
            float w = __shfl_sync(0xFFFFFFFF, dsrc, j) * dn;
            uint4 raw = *((const uint4*)(hbase + (size_t)s * 512 + 256) + lane);
            float2 f0 = __half22float2(*(__half2*)&raw.x);
            float2 f1 = __half22float2(*(__half2*)&raw.y);
            float2 f2 = __half22float2(*(__half2*)&raw.z);
            float2 f3 = __half22float2(*(__half2*)&raw.w);
            acc[0] += f0.x * w; acc[1] += f0.y * w; acc[2] += f1.x * w; acc[3] += f1.y * w;
            acc[4] += f2.x * w; acc[5] += f2.y * w; acc[6] += f3.x * w; acc[7] += f3.y * w;
        }
    }
    uint4 outw;
    __half2 p0 = __floats2half2_rn(acc[0], acc[1]);
    __half2 p1 = __floats2half2_rn(acc[2], acc[3]);
    __half2 p2 = __floats2half2_rn(acc[4], acc[5]);
    __half2 p3 = __floats2half2_rn(acc[6], acc[7]);
    outw.x = *(uint32_t*)&p0; outw.y = *(uint32_t*)&p1;
    outw.z = *(uint32_t*)&p2; outw.w = *(uint32_t*)&p3;
    *((uint4*)((__half*)out + (size_t)n * 512) + lane) = outw;
}

// ---------------- wmma GEMM (unchanged from R12): C_rows = A_rows @ B (N=256) ------
// BM=64, BN=256, BK=16; 8 warps in 2x4; each warp 2x4 m16n16k16 frags; fp32 accum.
// MODE 0: K=128, A fp16 @ half[0,128) of out row (pitch 512 h); C=zero, plain store.
// MODE 1: K=256, A fp16 @ half[0,256) of out row (pitch 512 h); C=zero, plain store.
// MODE 2: K=128, A = x (fp32, pitch 128); C preloaded (accumulate), ReLU store.
template <int MODE>
__global__ __launch_bounds__(256) void gemm_wmma(
    const float* __restrict__ Abuf, const float* __restrict__ B,
    float* __restrict__ C, int M)
{
    const int K = (MODE == 1) ? 256 : 128;
    __shared__ alignas(16) __half As[64][24];
    __shared__ alignas(16) __half Bs[16][272];
    int tid = threadIdx.x;
    int row0 = blockIdx.x * 64;
    int wid = tid >> 5;
    int warp_m = wid >> 2;
    int warp_n = wid & 3;
    const __half* hA = (const __half*)Abuf;

    wmma::fragment<wmma::accumulator, 16, 16, 16, float> cfrag[2][4];
    #pragma unroll
    for (int i = 0; i < 2; i++) {
        int fr = row0 + warp_m * 32 + i * 16;
        #pragma unroll
        for (int j = 0; j < 4; j++) {
            if (MODE == 2 && fr + 16 <= M)
                wmma::load_matrix_sync(cfrag[i][j],
                    &C[(size_t)fr * 256 + warp_n * 64 + j * 16], 256, wmma::mem_row_major);
            else
                wmma::fill_fragment(cfrag[i][j], 0.0f);
        }
    }

    for (int kt = 0; kt < K; kt += 16) {
        {
            int r = tid >> 2, c = (tid & 3) * 4;
            int gr = row0 + r;
            __half2 p0, p1;
            if (gr < M) {
                if (MODE != 2) {
                    uint2 raw = *(const uint2*)(hA + (size_t)gr * 512 + kt + c);
                    p0 = *(__half2*)&raw.x; p1 = *(__half2*)&raw.y;
                } else {
                    float4 v = *(const float4*)(Abuf + (size_t)gr * 128 + kt + c);
                    p0 = __floats2half2_rn(v.x, v.y);
                    p1 = __floats2half2_rn(v.z, v.w);
                }
            } else {
                p0 = __floats2half2_rn(0.f, 0.f); p1 = p0;
            }
            *(__half2*)&As[r][c]     = p0;
            *(__half2*)&As[r][c + 2] = p1;
        }
        #pragma unroll
        for (int i = tid; i < 512; i += 256) {
            int r = i >> 5, c = (i & 31) * 8;
            float4 v0 = *(const float4*)&B[(size_t)(kt + r) * 256 + c];
            float4 v1 = *(const float4*)&B[(size_t)(kt + r) * 256 + c + 4];
            *(__half2*)&Bs[r][c]     = __floats2half2_rn(v0.x, v0.y);
            *(__half2*)&Bs[r][c + 2] = __floats2half2_rn(v0.z, v0.w);
            *(__half2*)&Bs[r][c + 4] = __floats2half2_rn(v1.x, v1.y);
            *(__half2*)&Bs[r][c + 6] = __floats2half2_rn(v1.z, v1.w);
        }
        __syncthreads();

        wmma::fragment<wmma::matrix_a, 16, 16, 16, __half, wmma::row_major> afrag[2];
        wmma::fragment<wmma::matrix_b, 16, 16, 16, __half, wmma::row_major> bfrag[4];
        #pragma unroll
        for (int i = 0; i < 2; i++)
            wmma::load_matrix_sync(afrag[i], &As[warp_m * 32 + i * 16][0], 24);
        #pragma unroll
        for (int j = 0; j < 4; j++)
            wmma::load_matrix_sync(bfrag[j], &Bs[0][warp_n * 64 + j * 16], 272);
        #pragma unroll
        for (int i = 0; i < 2; i++)
            #pragma unroll
            for (int j = 0; j < 4; j++)
                wmma::mma_sync(cfrag[i][j], afrag[i], bfrag[j], cfrag[i][j]);
        __syncthreads();
    }

    #pragma unroll
    for (int i = 0; i < 2; i++) {
        int fr = row0 + warp_m * 32 + i * 16;
        if (fr + 16 > M) continue;
        #pragma unroll
        for (int j = 0; j < 4; j++) {
            if (MODE == 2) {
                #pragma unroll
                for (int e = 0; e < cfrag[i][j].num_elements; e++)
                    cfrag[i][j].x[e] = fmaxf(cfrag[i][j].x[e], 0.0f);
            }
            wmma::store_matrix_sync(&C[(size_t)fr * 256 + warp_n * 64 + j * 16],
                                    cfrag[i][j], 256, wmma::mem_row_major);
        }
    }
}

// ---------------- ln_to_h: h = relu(LN(z+b1)) -> half[256,512) ----------------
__global__ __launch_bounds__(256) void ln_to_h(
    float* __restrict__ out, const float* __restrict__ bias,
    const float* __restrict__ gamma, const float* __restrict__ beta, int M)
{
    int warp = (blockIdx.x * blockDim.x + threadIdx.x) >> 5;
    int lane = threadIdx.x & 31;
    if (warp >= M) return;
    const float4* rowp = (const float4*)(out + (size_t)warp * 256);

    float v[8];
    #pragma unroll
    for (int i = 0; i < 2; i++) {
        int f4 = lane + i * 32;
        float4 t = rowp[f4];
        float4 bb = ((const float4*)bias)[f4];
        v[i*4+0] = t.x + bb.x; v[i*4+1] = t.y + bb.y;
        v[i*4+2] = t.z + bb.z; v[i*4+3] = t.w + bb.w;
    }
    float s = 0.f, s2 = 0.f;
    #pragma unroll
    for (int i = 0; i < 8; i++) { s += v[i]; s2 += v[i] * v[i]; }
    #pragma unroll
    for (int o = 16; o > 0; o >>= 1) {
        s  += __shfl_xor_sync(0xFFFFFFFF, s,  o);
        s2 += __shfl_xor_sync(0xFFFFFFFF, s2, o);
    }
    float mean = s * (1.0f / 256.0f);
    float var  = s2 * (1.0f / 256.0f) - mean * mean;
    float rs   = rsqrtf(var + LN_EPS);

    #pragma unroll
    for (int i = 0; i < 2; i++) {
        int f4 = lane + i * 32;
        float4 gm = ((const float4*)gamma)[f4];
        float4 bt = ((const float4*)beta)[f4];
        float o0 = fmaxf((v[i*4+0]-mean)*rs*gm.x + bt.x, 0.f);
        float o1 = fmaxf((v[i*4+1]-mean)*rs*gm.y + bt.y, 0.f);
        float o2 = fmaxf((v[i*4+2]-mean)*rs*gm.z + bt.z, 0.f);
        float o3 = fmaxf((v[i*4+3]-mean)*rs*gm.w + bt.w, 0.f);
        __half2* hp = (__half2*)((__half*)out + (size_t)warp * 512 + 256 + f4 * 4);
        hp[0] = __floats2half2_rn(o0, o1);
        hp[1] = __floats2half2_rn(o2, o3);
    }
}

// ---------------- ln_inplace: u = LN(u + bias) + pb (fp32, no relu) ----------------
__global__ __launch_bounds__(256) void ln_inplace(
    float* __restrict__ out, const float* __restrict__ bias,
    const float* __restrict__ gamma, const float* __restrict__ beta,
    const float* __restrict__ pb, int M)
{
    int warp = (blockIdx.x * blockDim.x + threadIdx.x) >> 5;
    int lane = threadIdx.x & 31;
    if (warp >= M) return;
    float4* rowp = (float4*)(out + (size_t)warp * 256);

    float v[8];
    #pragma unroll
    for (int i = 0; i < 2; i++) {
        int f4 = lane + i * 32;
        float4 t = rowp[f4];
        float4 bb = ((const float4*)bias)[f4];
        v[i*4+0] = t.x + bb.x; v[i*4+1] = t.y + bb.y;
        v[i*4+2] = t.z + bb.z; v[i*4+3] = t.w + bb.w;
    }
    float s = 0.f, s2 = 0.f;
    #pragma unroll
    for (int i = 0; i < 8; i++) { s += v[i]; s2 += v[i] * v[i]; }
    #pragma unroll
    for (int o = 16; o > 0; o >>= 1) {
        s  += __shfl_xor_sync(0xFFFFFFFF, s,  o);
        s2 += __shfl_xor_sync(0xFFFFFFFF, s2, o);
    }
    float mean = s * (1.0f / 256.0f);
    float var  = s2 * (1.0f / 256.0f) - mean * mean;
    float rs   = rsqrtf(var + LN_EPS);

    #pragma unroll
    for (int i = 0; i < 2; i++) {
        int f4 = lane + i * 32;
        float4 gm = ((const float4*)gamma)[f4];
        float4 bt = ((const float4*)beta)[f4];
        float4 pv = ((const float4*)pb)[f4];
        float4 o;
        o.x = (v[i*4+0]-mean)*rs*gm.x + bt.x + pv.x;
        o.y = (v[i*4+1]-mean)*rs*gm.y + bt.y + pv.y;
        o.z = (v[i*4+2]-mean)*rs*gm.z + bt.z + pv.z;
        o.w = (v[i*4+3]-mean)*rs*gm.w + bt.w + pv.w;
        rowp[f4] = o;
    }
}

// ---------------- prewarm (best effort; all errors swallowed) ----------------
namespace {
struct Prewarm {
    Prewarm() {
        float* s = nullptr;
        cudaGetSymbolAddress((void**)&s, g_dinv);
        if (!s) { cudaGetLastError(); return; }
        void* p = nullptr;
        cudaGetSymbolAddress(&p, g_csr);
        detect_kernel<<<1, 1>>>(s);
        zero_cnt_kernel<<<(NN + 255) / 256, 256>>>();
        scan_kernel<<<1, 1024>>>();
        cudaDeviceSynchronize();
        cudaGetLastError();
    }
};
static Prewarm g_prewarm;
}

// ---------------- launch ----------------
extern "C" void kernel_launch(void* const* d_in, const int* in_sizes, int n_in,
                              void* d_out, int out_size)
{
    const float* x      = (const float*)d_in[0];
    const void*  ei     = d_in[1];
    const float* W1     = (const float*)d_in[2];
    const float* b1     = (const float*)d_in[3];
    const float* W2     = (const float*)d_in[4];
    const float* b2     = (const float*)d_in[5];
    const float* ln1_g  = (const float*)d_in[6];
    const float* ln1_b  = (const float*)d_in[7];
    const float* ln2_g  = (const float*)d_in[8];
    const float* ln2_b  = (const float*)d_in[9];
    const float* proj_W = (const float*)d_in[10];
    const float* proj_b = (const float*)d_in[11];
    float* out = (float*)d_out;

    int nb_n   = (NN + 255) / 256;
    int nb_e   = (NE + 255) / 256;
    int nb_row = (NN * 32 + 255) / 256;   // warp-per-node kernels
    int nb_g   = (NN + 63) / 64;

    // ---- CSR build (once; reused by both layers) ----
    detect_kernel<<<1, 1>>>(ei);
    zero_cnt_kernel<<<nb_n, 256>>>();
    deg_count_kernel<<<nb_e, 256>>>(ei, NE);
    scan_kernel<<<1, 1024>>>();
    fill_kernel<<<nb_e, 256>>>(ei, NE);

    // ---- layer 1: t = A_hat x (gather, fp32 accum) ; z = t@W1 ; h = relu(LN(z+b1)) ----
    gather_x<<<nb_row, 256>>>(x, out);
    gemm_wmma<0><<<nb_g, 256>>>(out, W1, out, NN);
    ln_to_h<<<nb_row, 256>>>(out, b1, ln1_g, ln1_b, NN);

    // ---- layer 2: s = A_hat h (gather) ; u = s@W2 ; u = LN(u+b2)+proj_b ----
    gather_h<<<nb_row, 256>>>(out);
    gemm_wmma<1><<<nb_g, 256>>>(out, W2, out, NN);
    ln_inplace<<<nb_row, 256>>>(out, b2, ln2_g, ln2_b, proj_b, NN);

    // ---- out = relu(u + x@proj_W) (accumulate into preloaded C, relu) ----
    gemm_wmma<2><<<nb_g, 256>>>(x, proj_W, out, NN);
}